// round 12
// baseline (speedup 1.0000x reference)
#include <cuda_runtime.h>
#include <cuda_bf16.h>
#include <cstdint>

// InnerProduct_65429531787441 — HMMA bf16-split, v2.
//   X [B,50,64] f32, Theta [128,50] f32
//   proj = einsum("df,bfe->bde"); out[b,d] = sum_e proj^2 -> [B,128] f32
//
// vs R8: (a) K truncated to 48 on the tensor pipe; k=48,49 applied as an
// exact fp32 rank-2 update in the epilogue (kills the 28% K-pad waste and
// improves accuracy). (b) 512-thread CTAs, M16xN32 warp tiles, Theta hi+lo
// fragments in smem -> regs fit __launch_bounds__(512,2) = 50% occupancy.
// (c) one __syncthreads per batch (red parity-double-buffered).

#define F_DIM 50
#define E_DIM 64
#define D_DIM 128
#define NTHREADS 512
#define GRID 296
#define KS_N 3                     // dense k16 chunks: k = 0..47

struct Smem {
    uint32_t A[2][8][KS_N][32][4];     // [hi/lo][mb][ks][lane][rg]   24 KB
    uint32_t BH[2][KS_N * 8 * 32 * 2]; // [buf][((ks*8+nt)*32+l)*2+r] 12 KB
    uint32_t BL[2][KS_N * 8 * 32 * 2]; //                             12 KB
    float    Xt[2][128];               // [buf][e: row48 | 64+e: row49] 1 KB
    float    red[2][2][128];           // [parity][nh][d]               2 KB
};

__device__ __forceinline__ void mma_bf16(float* c, const uint32_t* a,
                                         uint32_t b0, uint32_t b1) {
    asm("mma.sync.aligned.m16n8k16.row.col.f32.bf16.bf16.f32 "
        "{%0,%1,%2,%3}, {%4,%5,%6,%7}, {%8,%9}, {%0,%1,%2,%3};"
        : "+f"(c[0]), "+f"(c[1]), "+f"(c[2]), "+f"(c[3])
        : "r"(a[0]), "r"(a[1]), "r"(a[2]), "r"(a[3]), "r"(b0), "r"(b1));
}

__device__ __forceinline__ uint32_t split_pack(float v0, float v1,
                                               uint32_t& lo_out) {
    __nv_bfloat16 h0 = __float2bfloat16(v0);
    __nv_bfloat16 h1 = __float2bfloat16(v1);
    __nv_bfloat16 l0 = __float2bfloat16(v0 - __bfloat162float(h0));
    __nv_bfloat16 l1 = __float2bfloat16(v1 - __bfloat162float(h1));
    __nv_bfloat162 hp(h0, h1), lp(l0, l1);
    lo_out = *reinterpret_cast<uint32_t*>(&lp);
    return *reinterpret_cast<uint32_t*>(&hp);
}

__global__ void __launch_bounds__(NTHREADS, 2)
ip_hmma2(const float* __restrict__ X, const float* __restrict__ Theta,
         float* __restrict__ out, int Btot) {
    extern __shared__ char smem_raw[];
    Smem& S = *reinterpret_cast<Smem*>(smem_raw);

    const int t  = threadIdx.x;
    const int w  = t >> 5;
    const int l  = t & 31;
    const int mb = w & 7;      // M16 row block: rows [16*mb, 16*mb+16)
    const int nh = w >> 3;     // N32 col half:  cols [32*nh, 32*nh+32)
    const int lg = l >> 2;     // quad group (0..7)
    const int la = l & 3;      // lane in quad

    // ---- Prologue: Theta fragments (hi+lo) into smem, once ----
    for (int i = t; i < 8 * KS_N * 4 * 32; i += NTHREADS) {
        int rg   = i & 3;
        int lane = (i >> 2) & 31;
        int ms   = i >> 7;                  // mb*3 + ks
        int ks   = ms % KS_N;
        int mbp  = ms / KS_N;
        int row  = mbp * 16 + (lane >> 2) + ((rg & 1) ? 8 : 0);
        int k    = ks * 16 + (lane & 3) * 2 + ((rg & 2) ? 8 : 0);   // <= 46
        uint32_t lo;
        uint32_t hi = split_pack(Theta[row * F_DIM + k],
                                 Theta[row * F_DIM + k + 1], lo);
        S.A[0][mbp][ks][lane][rg] = hi;
        S.A[1][mbp][ks][lane][rg] = lo;
    }

    // Exact fp32 Theta tail (k = 48, 49) for this warp's two row slots.
    const float t48a = Theta[(mb * 16 + lg)     * F_DIM + 48];
    const float t49a = Theta[(mb * 16 + lg)     * F_DIM + 49];
    const float t48b = Theta[(mb * 16 + lg + 8) * F_DIM + 48];
    const float t49b = Theta[(mb * 16 + lg + 8) * F_DIM + 49];

    const int stride = (int)gridDim.x;
    const int b0 = (int)blockIdx.x;

    float xr[KS_N][2];   // this thread's 3 fragment k-pairs (combos w*3+j)
    float xt = 0.f;      // one element of rows 48/49 (threads 0..127)

    auto prefetch = [&](int b) {
        const float* Xb = X + (size_t)b * (F_DIM * E_DIM);
        #pragma unroll
        for (int j = 0; j < KS_N; j++) {
            int combo = w * 3 + j;                       // 0..47
            int ks = combo >> 4, r = (combo >> 3) & 1, nt = combo & 7;
            int fp = ks * 8 + r * 4 + la;                // k = 2*fp (< 48)
            int e  = nt * 8 + lg;
            xr[j][0] = __ldg(Xb + 2 * fp * E_DIM + e);
            xr[j][1] = __ldg(Xb + (2 * fp + 1) * E_DIM + e);
        }
        if (t < 128) xt = __ldg(Xb + (48 + (t >> 6)) * E_DIM + (t & 63));
    };
    auto convert = [&](int buf) {
        #pragma unroll
        for (int j = 0; j < KS_N; j++) {
            int combo = w * 3 + j;
            int ks = combo >> 4, r = (combo >> 3) & 1, nt = combo & 7;
            int idx = ((ks * 8 + nt) * 32 + l) * 2 + r;
            uint32_t lo;
            uint32_t hi = split_pack(xr[j][0], xr[j][1], lo);
            S.BH[buf][idx] = hi;
            S.BL[buf][idx] = lo;
        }
        if (t < 128) S.Xt[buf][t] = xt;
    };

    if (b0 < Btot) { prefetch(b0); convert(0); }
    __syncthreads();

    int i = 0;
    for (int b = b0; b < Btot; b += stride, i++) {
        const int cur = i & 1;
        const int bn  = b + stride;
        if (bn < Btot) prefetch(bn);         // DRAM overlapped with HMMA

        float C[4][4];
        #pragma unroll
        for (int ntl = 0; ntl < 4; ntl++)
            #pragma unroll
            for (int rg = 0; rg < 4; rg++) C[ntl][rg] = 0.f;

        // ---- mainloop: 36 dense HMMA per warp ----
        #pragma unroll
        for (int ks = 0; ks < KS_N; ks++) {
            uint4 ahv = *reinterpret_cast<const uint4*>(&S.A[0][mb][ks][l][0]);
            uint4 alv = *reinterpret_cast<const uint4*>(&S.A[1][mb][ks][l][0]);
            uint32_t AH[4] = {ahv.x, ahv.y, ahv.z, ahv.w};
            uint32_t AL[4] = {alv.x, alv.y, alv.z, alv.w};
            #pragma unroll
            for (int ntl = 0; ntl < 4; ntl++) {
                int nt = nh * 4 + ntl;
                int base = ((ks * 8 + nt) * 32 + l) * 2;
                uint2 bh = *reinterpret_cast<const uint2*>(&S.BH[cur][base]);
                uint2 bl = *reinterpret_cast<const uint2*>(&S.BL[cur][base]);
                mma_bf16(C[ntl], AH, bh.x, bh.y);   // Ah*Bh
                mma_bf16(C[ntl], AH, bl.x, bl.y);   // Ah*Bl
                mma_bf16(C[ntl], AL, bh.x, bh.y);   // Al*Bh
            }
        }

        // ---- exact rank-2 update for k = 48, 49 ----
        #pragma unroll
        for (int ntl = 0; ntl < 4; ntl++) {
            int col = nh * 32 + ntl * 8 + 2 * la;
            float2 x48 = *reinterpret_cast<const float2*>(&S.Xt[cur][col]);
            float2 x49 = *reinterpret_cast<const float2*>(&S.Xt[cur][64 + col]);
            C[ntl][0] += t48a * x48.x + t49a * x49.x;
            C[ntl][1] += t48a * x48.y + t49a * x49.y;
            C[ntl][2] += t48b * x48.x + t49b * x49.x;
            C[ntl][3] += t48b * x48.y + t49b * x49.y;
        }

        // ---- epilogue: sum_e proj^2 ----
        float s0 = 0.f, s1 = 0.f;
        #pragma unroll
        for (int ntl = 0; ntl < 4; ntl++) {
            s0 = fmaf(C[ntl][0], C[ntl][0], fmaf(C[ntl][1], C[ntl][1], s0));
            s1 = fmaf(C[ntl][2], C[ntl][2], fmaf(C[ntl][3], C[ntl][3], s1));
        }
        s0 += __shfl_xor_sync(0xffffffffu, s0, 1);
        s0 += __shfl_xor_sync(0xffffffffu, s0, 2);
        s1 += __shfl_xor_sync(0xffffffffu, s1, 1);
        s1 += __shfl_xor_sync(0xffffffffu, s1, 2);
        if (la == 0) {
            S.red[cur][nh][mb * 16 + lg]     = s0;
            S.red[cur][nh][mb * 16 + lg + 8] = s1;
        }

        if (bn < Btot) convert(cur ^ 1);     // fill other buffer pre-sync

        __syncthreads();                      // single barrier per batch

        if (t < D_DIM)
            out[(size_t)b * D_DIM + t] = S.red[cur][0][t] + S.red[cur][1][t];
    }
}

extern "C" void kernel_launch(void* const* d_in, const int* in_sizes, int n_in,
                              void* d_out, int out_size) {
    int xi = 0, ti = 1;
    if (n_in >= 2 && in_sizes[0] < in_sizes[1]) { xi = 1; ti = 0; }

    const float* X     = (const float*)d_in[xi];
    const float* Theta = (const float*)d_in[ti];
    float*       out   = (float*)d_out;
    int Btot = in_sizes[xi] / (F_DIM * E_DIM);

    cudaFuncSetAttribute(ip_hmma2, cudaFuncAttributeMaxDynamicSharedMemorySize,
                         (int)sizeof(Smem));
    ip_hmma2<<<GRID, NTHREADS, sizeof(Smem)>>>(X, Theta, out, Btot);
}

// round 14
// speedup vs baseline: 1.1985x; 1.1985x over previous
#include <cuda_runtime.h>
#include <cuda_bf16.h>
#include <cstdint>

// InnerProduct_65429531787441 — HMMA bf16-split, v3 (R8 structure + K-trunc).
//   X [B,50,64] f32, Theta [128,50] f32
//   proj = einsum("df,bfe->bde"); out[b,d] = sum_e proj^2 -> [B,128] f32
//
// R8 core (proven 61% tensor duty): 256 thr, warp = M32xN32 tile, Theta-hi
// fragments register-resident, Theta-lo in smem, X streamed LDG->convert->
// frag STS double-buffered.
// New vs R8: K truncated to 48 on tensor pipe, k=48..49 as exact fp32
// rank-2 update (12.5% less HMMA work, better accuracy); one sync/batch
// (red parity-buffered); B frags stored (r0,r1)-adjacent for LDS.64.

#define F_DIM 50
#define E_DIM 64
#define D_DIM 128
#define NTHREADS 256
#define GRID 296
#define KS_N 3                       // dense k16 chunks (k < 48)

struct Smem {
    uint32_t Al[4][2][KS_N][32][4];     // [mblk][mt][ks][lane][rg]  12 KB
    uint32_t BH[2][KS_N * 8 * 32 * 2];  // [buf][((ks*8+nt)*32+l)*2+r] 12 KB
    uint32_t BL[2][KS_N * 8 * 32 * 2];  //                            12 KB
    float    Xt[2][128];                // [buf][e | 64+e] rows 48,49   1 KB
    float    red[2][2][128];            // [parity][nh][d]              2 KB
};

__device__ __forceinline__ void mma_bf16(float* c, const uint32_t* a,
                                         uint32_t b0, uint32_t b1) {
    asm("mma.sync.aligned.m16n8k16.row.col.f32.bf16.bf16.f32 "
        "{%0,%1,%2,%3}, {%4,%5,%6,%7}, {%8,%9}, {%0,%1,%2,%3};"
        : "+f"(c[0]), "+f"(c[1]), "+f"(c[2]), "+f"(c[3])
        : "r"(a[0]), "r"(a[1]), "r"(a[2]), "r"(a[3]), "r"(b0), "r"(b1));
}

__device__ __forceinline__ uint32_t split_pack(float v0, float v1,
                                               uint32_t& lo_out) {
    __nv_bfloat16 h0 = __float2bfloat16(v0);
    __nv_bfloat16 h1 = __float2bfloat16(v1);
    __nv_bfloat16 l0 = __float2bfloat16(v0 - __bfloat162float(h0));
    __nv_bfloat16 l1 = __float2bfloat16(v1 - __bfloat162float(h1));
    __nv_bfloat162 hp(h0, h1), lp(l0, l1);
    lo_out = *reinterpret_cast<uint32_t*>(&lp);
    return *reinterpret_cast<uint32_t*>(&hp);
}

__global__ void __launch_bounds__(NTHREADS, 2)
ip_hmma3(const float* __restrict__ X, const float* __restrict__ Theta,
         float* __restrict__ out, int Btot) {
    extern __shared__ char smem_raw[];
    Smem& S = *reinterpret_cast<Smem*>(smem_raw);

    const int t    = threadIdx.x;
    const int w    = t >> 5;
    const int l    = t & 31;
    const int mblk = w & 3;    // M32 row block
    const int nh   = w >> 2;   // N32 col half
    const int lg   = l >> 2;   // quad group (0..7)
    const int la   = l & 3;    // lane in quad

    // ---- Theta fragments: hi in registers, lo to shared (once) ----
    uint32_t Ah[2][KS_N][4];
    #pragma unroll
    for (int mt = 0; mt < 2; mt++)
        #pragma unroll
        for (int ks = 0; ks < KS_N; ks++)
            #pragma unroll
            for (int rg = 0; rg < 4; rg++) {
                int row = mblk * 32 + mt * 16 + lg + ((rg & 1) ? 8 : 0);
                int k   = ks * 16 + la * 2 + ((rg & 2) ? 8 : 0);   // <= 46
                uint32_t lo;
                Ah[mt][ks][rg] = split_pack(Theta[row * F_DIM + k],
                                            Theta[row * F_DIM + k + 1], lo);
                if (nh == 0) S.Al[mblk][mt][ks][l][rg] = lo;
            }

    // Exact fp32 tail Theta (k = 48,49) for this warp's 4 row slots.
    float tT[2][2][2];   // [mt][rowhalf][k-48]
    #pragma unroll
    for (int mt = 0; mt < 2; mt++)
        #pragma unroll
        for (int h = 0; h < 2; h++) {
            int row = mblk * 32 + mt * 16 + lg + h * 8;
            tT[mt][h][0] = Theta[row * F_DIM + 48];
            tT[mt][h][1] = Theta[row * F_DIM + 49];
        }

    const int stride = (int)gridDim.x;
    const int b0 = (int)blockIdx.x;

    float xr[6][2];   // 48 combos = 8 warps x 6/thread-quad-slot
    float xt = 0.f;

    auto prefetch = [&](int b) {
        const float* Xb = X + (size_t)b * (F_DIM * E_DIM);
        #pragma unroll
        for (int j = 0; j < 6; j++) {
            int combo = w * 6 + j;                      // 0..47
            int ks = combo >> 4, r = (combo >> 3) & 1, nt = combo & 7;
            int fp = ks * 8 + r * 4 + la;               // k = 2*fp < 48
            int e  = nt * 8 + lg;
            xr[j][0] = __ldg(Xb + 2 * fp * E_DIM + e);
            xr[j][1] = __ldg(Xb + (2 * fp + 1) * E_DIM + e);
        }
        if (t < 128) xt = __ldg(Xb + (48 + (t >> 6)) * E_DIM + (t & 63));
    };
    auto convert = [&](int buf) {
        #pragma unroll
        for (int j = 0; j < 6; j++) {
            int combo = w * 6 + j;
            int ks = combo >> 4, r = (combo >> 3) & 1, nt = combo & 7;
            int idx = ((ks * 8 + nt) * 32 + l) * 2 + r;
            uint32_t lo;
            uint32_t hi = split_pack(xr[j][0], xr[j][1], lo);
            S.BH[buf][idx] = hi;
            S.BL[buf][idx] = lo;
        }
        if (t < 128) S.Xt[buf][t] = xt;
    };

    if (b0 < Btot) { prefetch(b0); convert(0); }
    __syncthreads();

    int i = 0;
    for (int b = b0; b < Btot; b += stride, i++) {
        const int cur = i & 1;
        const int bn  = b + stride;
        if (bn < Btot) prefetch(bn);          // DRAM under HMMA

        float C[2][4][4];
        #pragma unroll
        for (int mt = 0; mt < 2; mt++)
            #pragma unroll
            for (int ntl = 0; ntl < 4; ntl++)
                #pragma unroll
                for (int rg = 0; rg < 4; rg++) C[mt][ntl][rg] = 0.f;

        // ---- mainloop: 72 HMMA per warp ----
        #pragma unroll
        for (int ks = 0; ks < KS_N; ks++) {
            uint32_t AL0[4], AL1[4];
            {
                uint4 a0 = *reinterpret_cast<const uint4*>(&S.Al[mblk][0][ks][l][0]);
                uint4 a1 = *reinterpret_cast<const uint4*>(&S.Al[mblk][1][ks][l][0]);
                AL0[0] = a0.x; AL0[1] = a0.y; AL0[2] = a0.z; AL0[3] = a0.w;
                AL1[0] = a1.x; AL1[1] = a1.y; AL1[2] = a1.z; AL1[3] = a1.w;
            }
            #pragma unroll
            for (int ntl = 0; ntl < 4; ntl++) {
                int nt = nh * 4 + ntl;
                int base = ((ks * 8 + nt) * 32 + l) * 2;
                uint2 bh = *reinterpret_cast<const uint2*>(&S.BH[cur][base]);
                uint2 bl = *reinterpret_cast<const uint2*>(&S.BL[cur][base]);
                mma_bf16(C[0][ntl], Ah[0][ks], bh.x, bh.y);
                mma_bf16(C[1][ntl], Ah[1][ks], bh.x, bh.y);
                mma_bf16(C[0][ntl], Ah[0][ks], bl.x, bl.y);
                mma_bf16(C[1][ntl], Ah[1][ks], bl.x, bl.y);
                mma_bf16(C[0][ntl], AL0,       bh.x, bh.y);
                mma_bf16(C[1][ntl], AL1,       bh.x, bh.y);
            }
        }

        // ---- exact rank-2 update (k = 48, 49) on the fma pipe ----
        #pragma unroll
        for (int ntl = 0; ntl < 4; ntl++) {
            int e0 = nh * 32 + ntl * 8 + 2 * la;
            float2 x48 = *reinterpret_cast<const float2*>(&S.Xt[cur][e0]);
            float2 x49 = *reinterpret_cast<const float2*>(&S.Xt[cur][64 + e0]);
            #pragma unroll
            for (int mt = 0; mt < 2; mt++) {
                C[mt][ntl][0] = fmaf(tT[mt][0][0], x48.x,
                                fmaf(tT[mt][0][1], x49.x, C[mt][ntl][0]));
                C[mt][ntl][1] = fmaf(tT[mt][0][0], x48.y,
                                fmaf(tT[mt][0][1], x49.y, C[mt][ntl][1]));
                C[mt][ntl][2] = fmaf(tT[mt][1][0], x48.x,
                                fmaf(tT[mt][1][1], x49.x, C[mt][ntl][2]));
                C[mt][ntl][3] = fmaf(tT[mt][1][0], x48.y,
                                fmaf(tT[mt][1][1], x49.y, C[mt][ntl][3]));
            }
        }

        // ---- epilogue: sum_e proj^2, reduce within quad ----
        float s[2][2] = {{0.f, 0.f}, {0.f, 0.f}};
        #pragma unroll
        for (int mt = 0; mt < 2; mt++)
            #pragma unroll
            for (int ntl = 0; ntl < 4; ntl++) {
                s[mt][0] = fmaf(C[mt][ntl][0], C[mt][ntl][0],
                           fmaf(C[mt][ntl][1], C[mt][ntl][1], s[mt][0]));
                s[mt][1] = fmaf(C[mt][ntl][2], C[mt][ntl][2],
                           fmaf(C[mt][ntl][3], C[mt][ntl][3], s[mt][1]));
            }
        #pragma unroll
        for (int mt = 0; mt < 2; mt++)
            #pragma unroll
            for (int h = 0; h < 2; h++) {
                float v = s[mt][h];
                v += __shfl_xor_sync(0xffffffffu, v, 1);
                v += __shfl_xor_sync(0xffffffffu, v, 2);
                s[mt][h] = v;
            }
        if (la == 0) {
            #pragma unroll
            for (int mt = 0; mt < 2; mt++) {
                S.red[cur][nh][mblk * 32 + mt * 16 + lg]     = s[mt][0];
                S.red[cur][nh][mblk * 32 + mt * 16 + lg + 8] = s[mt][1];
            }
        }

        if (bn < Btot) convert(cur ^ 1);      // other buffer, pre-sync

        __syncthreads();                       // single barrier per batch

        if (t < D_DIM)
            out[(size_t)b * D_DIM + t] = S.red[cur][0][t] + S.red[cur][1][t];
    }
}

extern "C" void kernel_launch(void* const* d_in, const int* in_sizes, int n_in,
                              void* d_out, int out_size) {
    int xi = 0, ti = 1;
    if (n_in >= 2 && in_sizes[0] < in_sizes[1]) { xi = 1; ti = 0; }

    const float* X     = (const float*)d_in[xi];
    const float* Theta = (const float*)d_in[ti];
    float*       out   = (float*)d_out;
    int Btot = in_sizes[xi] / (F_DIM * E_DIM);

    cudaFuncSetAttribute(ip_hmma3, cudaFuncAttributeMaxDynamicSharedMemorySize,
                         (int)sizeof(Smem));
    ip_hmma3<<<GRID, NTHREADS, sizeof(Smem)>>>(X, Theta, out, Btot);
}